// round 11
// baseline (speedup 1.0000x reference)
#include <cuda_runtime.h>
#include <cuda_bf16.h>
#include <math.h>
#include <math_constants.h>
#include <cstdint>

// Problem constants (fixed shapes per reference)
#define NN    50000                // nodes
#define NE    800000               // edges (without self loops)
#define ET    (NE + NN)            // edges + self loops
#define D1    128                  // HEADS*CH  (also F_IN)
#define HEADS 4
#define CH    32
#define CLS   40
#define SCANB 1024
#define NBLK  ((NN + SCANB - 1) / SCANB)   // 49
#define NHALF 25600                // node1/gemm2 pipeline split (mult of 64)

typedef unsigned long long ull;

// ---------------- scratch (static device allocations) ----------------
static __device__ float g_xl1[(size_t)NN * D1];
static __device__ float g_xr1[(size_t)NN * D1];
static __device__ float g_h  [(size_t)NN * D1];
static __device__ float g_xl2[(size_t)NN * CLS];
static __device__ float g_xr2[(size_t)NN * CLS];
static __device__ int   g_src[ET];
static __device__ int   g_dst[ET];
static __device__ int   g_deg[NN];          // zeroed in scan3 (BSS-zero first run)
static __device__ int   g_incl[NBLK * SCANB];
static __device__ int   g_bsum[NBLK];
static __device__ int   g_rowptr[NN + 1];
static __device__ int   g_cursor[NN];
static __device__ int   g_csrc[ET];
// split-bf16 weight tiles, [n][k] layout (n = output col, k contiguous)
static __device__ __nv_bfloat16 g_wlh[128 * 128];
static __device__ __nv_bfloat16 g_wll[128 * 128];
static __device__ __nv_bfloat16 g_wrh[128 * 128];
static __device__ __nv_bfloat16 g_wrl[128 * 128];
static __device__ __nv_bfloat16 g_w2h[80 * 128];   // layer2 stacked [l|r]
static __device__ __nv_bfloat16 g_w2l[80 * 128];

// ---------------- helpers ----------------
__device__ __forceinline__ float lrelu(float v) {
    return (v > 0.f) ? v : 0.2f * v;
}

#define MMA_BF16(d, a, b0, b1)                                                 \
    asm volatile("mma.sync.aligned.m16n8k16.row.col.f32.bf16.bf16.f32 "        \
        "{%0,%1,%2,%3}, {%4,%5,%6,%7}, {%8,%9}, {%0,%1,%2,%3};"                \
        : "+f"((d)[0]), "+f"((d)[1]), "+f"((d)[2]), "+f"((d)[3])               \
        : "r"((a)[0]), "r"((a)[1]), "r"((a)[2]), "r"((a)[3]), "r"(b0), "r"(b1))

__device__ __forceinline__ void split2(float2 p, uint32_t& hi, uint32_t& lo) {
    __nv_bfloat16 hx = __float2bfloat16(p.x);
    __nv_bfloat16 hy = __float2bfloat16(p.y);
    __nv_bfloat16 lx = __float2bfloat16(p.x - __bfloat162float(hx));
    __nv_bfloat16 ly = __float2bfloat16(p.y - __bfloat162float(hy));
    __nv_bfloat162 h2(hx, hy), l2(lx, ly);
    hi = *reinterpret_cast<uint32_t*>(&h2);
    lo = *reinterpret_cast<uint32_t*>(&l2);
}
__device__ __forceinline__ void splitw(float v, __nv_bfloat16* ph, __nv_bfloat16* pl) {
    __nv_bfloat16 h = __float2bfloat16(v);
    *ph = h;
    *pl = __float2bfloat16(v - __bfloat162float(h));
}

// ---------------- CSR build (4 kernels) ---------------------------------
// conv: detect int64 per block (64 odd-word samples) + convert + histogram
__global__ void conv_hist_kernel(const int* __restrict__ w) {
    int nz = 0;
    for (int k = threadIdx.x; k < 64; k += blockDim.x)
        nz |= (w[2 * k + 1] != 0);
    int is64 = __syncthreads_or(nz) ? 0 : 1;

    int e = blockIdx.x * blockDim.x + threadIdx.x;
    if (e >= ET) return;
    int src, dst;
    if (e >= NE) {
        src = e - NE; dst = src;
    } else if (is64) {
        src = w[2 * e];
        dst = w[2 * (NE + e)];
    } else {
        src = w[e];
        dst = w[NE + e];
    }
    g_src[e] = src;
    g_dst[e] = dst;
    atomicAdd(&g_deg[dst], 1);
}

__global__ void scan1_kernel() {
    __shared__ int sm[SCANB];
    int t = threadIdx.x;
    int i = blockIdx.x * SCANB + t;
    sm[t] = (i < NN) ? g_deg[i] : 0;
    __syncthreads();
    for (int off = 1; off < SCANB; off <<= 1) {
        int add = (t >= off) ? sm[t - off] : 0;
        __syncthreads();
        sm[t] += add;
        __syncthreads();
    }
    g_incl[i] = sm[t];
    if (t == SCANB - 1) g_bsum[blockIdx.x] = sm[t];
}

// scan3 with scan2 fused: every block locally scans the 49 block sums
__global__ void scan3_kernel() {
    __shared__ int sb[64];
    int t = threadIdx.x;
    if (t < 64) sb[t] = (t < NBLK) ? g_bsum[t] : 0;
    __syncthreads();
    for (int off = 1; off < 64; off <<= 1) {
        int add = (t < 64 && t >= off) ? sb[t - off] : 0;
        __syncthreads();
        if (t < 64) sb[t] += add;
        __syncthreads();
    }
    int i = blockIdx.x * blockDim.x + t;
    if (i >= NN) return;
    int b = i >> 10;
    int boff = (b == 0) ? 0 : sb[b - 1];
    int incl = g_incl[i] + boff;
    g_rowptr[i + 1] = incl;
    g_cursor[i] = incl - g_deg[i];
    g_deg[i] = 0;              // reset for next replay
    if (i == 0) g_rowptr[0] = 0;
}

__global__ void scatter_kernel() {
    int e = blockIdx.x * blockDim.x + threadIdx.x;
    if (e >= ET) return;
    int dst = g_dst[e];
    int pos = atomicAdd(&g_cursor[dst], 1);
    g_csrc[pos] = g_src[e];
}

// ---------------- weight prep: both layers, split bf16 [n][k] -----------
__global__ void wprep_kernel(const float* __restrict__ wl1,
                             const float* __restrict__ wr1,
                             const float* __restrict__ wl2,
                             const float* __restrict__ wr2) {
    int i = blockIdx.x * blockDim.x + threadIdx.x;
    if (i < 128 * 128) {
        int k = i >> 7, n = i & 127;
        int o = n * 128 + k;
        splitw(wl1[i], &g_wlh[o], &g_wll[o]);
        splitw(wr1[i], &g_wrh[o], &g_wrl[o]);
    } else if (i < 128 * 128 + 80 * 128) {
        int j = i - 128 * 128;
        int n = j >> 7, k = j & 127;
        float v = (n < CLS) ? wl2[k * CLS + n] : wr2[k * CLS + (n - CLS)];
        splitw(v, &g_w2h[j], &g_w2l[j]);
    }
}

// ---------------- layer 1 GEMM via mma.sync bf16 (split, fp32 accum) ----
// 256 threads = 8 warps, 64 rows/block, no SMEM (weights L1-resident).
// Warp: mw = wid&3 -> rows 16*mw..+15; nh = wid>>2 -> cols 64*nh..+63.
__global__ __launch_bounds__(256) void gemm1_mma_kernel(const float* __restrict__ x) {
    int lane = threadIdx.x & 31, wid = threadIdx.x >> 5;
    int g = lane >> 2, tg = lane & 3;
    int mw = wid & 3, nh = wid >> 2;
    int rowg  = blockIdx.x * 64 + mw * 16 + g;
    int rowg8 = rowg + 8;
    int r0 = (rowg  < NN) ? rowg  : (NN - 1);
    int r8 = (rowg8 < NN) ? rowg8 : (NN - 1);
    const float* xr0 = x + (size_t)r0 * D1;
    const float* xr8 = x + (size_t)r8 * D1;

    uint32_t ah[8][4], al[8][4];
    #pragma unroll
    for (int kc = 0; kc < 8; kc++) {
        int k0 = kc * 16 + 2 * tg;
        split2(*reinterpret_cast<const float2*>(xr0 + k0),     ah[kc][0], al[kc][0]);
        split2(*reinterpret_cast<const float2*>(xr8 + k0),     ah[kc][1], al[kc][1]);
        split2(*reinterpret_cast<const float2*>(xr0 + k0 + 8), ah[kc][2], al[kc][2]);
        split2(*reinterpret_cast<const float2*>(xr8 + k0 + 8), ah[kc][3], al[kc][3]);
    }

    const uint32_t* wh32[2] = {reinterpret_cast<const uint32_t*>(g_wlh),
                               reinterpret_cast<const uint32_t*>(g_wrh)};
    const uint32_t* wl32[2] = {reinterpret_cast<const uint32_t*>(g_wll),
                               reinterpret_cast<const uint32_t*>(g_wrl)};
    #pragma unroll
    for (int wsel = 0; wsel < 2; wsel++) {
        const uint32_t* WH = wh32[wsel];
        const uint32_t* WL = wl32[wsel];
        float acc[8][4];
        #pragma unroll
        for (int nt = 0; nt < 8; nt++)
            acc[nt][0] = acc[nt][1] = acc[nt][2] = acc[nt][3] = 0.f;
        #pragma unroll
        for (int kc = 0; kc < 8; kc++) {
            #pragma unroll
            for (int nt = 0; nt < 8; nt++) {
                int nrow = nh * 64 + nt * 8 + g;
                int idx = nrow * 64 + kc * 8 + tg;   // uint32 units (2 bf16)
                uint32_t bh0 = __ldg(&WH[idx]);
                uint32_t bh1 = __ldg(&WH[idx + 4]);
                uint32_t bl0 = __ldg(&WL[idx]);
                uint32_t bl1 = __ldg(&WL[idx + 4]);
                MMA_BF16(acc[nt], ah[kc], bh0, bh1);
                MMA_BF16(acc[nt], al[kc], bh0, bh1);
                MMA_BF16(acc[nt], ah[kc], bl0, bl1);
            }
        }
        float* dst = wsel ? g_xr1 : g_xl1;
        #pragma unroll
        for (int nt = 0; nt < 8; nt++) {
            int col = nh * 64 + nt * 8 + 2 * tg;
            if (rowg < NN)
                *reinterpret_cast<float2*>(dst + (size_t)rowg * D1 + col) =
                    make_float2(acc[nt][0], acc[nt][1]);
            if (rowg8 < NN)
                *reinterpret_cast<float2*>(dst + (size_t)rowg8 * D1 + col) =
                    make_float2(acc[nt][2], acc[nt][3]);
        }
    }
}

// ---------------- layer 2 GEMM via mma.sync (N=80 stacked, no SMEM) -----
// 256 threads = 8 warps, 64 rows/block. nh = wid>>2 selects l/r 40-col half.
__global__ __launch_bounds__(256) void gemm2_mma_kernel(int nbeg, int nend) {
    int lane = threadIdx.x & 31, wid = threadIdx.x >> 5;
    int g = lane >> 2, tg = lane & 3;
    int mw = wid & 3, nh = wid >> 2;
    int rowg  = nbeg + blockIdx.x * 64 + mw * 16 + g;
    int rowg8 = rowg + 8;
    int r0 = (rowg  < NN) ? rowg  : (NN - 1);
    int r8 = (rowg8 < NN) ? rowg8 : (NN - 1);
    const float* hr0 = g_h + (size_t)r0 * D1;
    const float* hr8 = g_h + (size_t)r8 * D1;

    uint32_t ah[8][4], al[8][4];
    #pragma unroll
    for (int kc = 0; kc < 8; kc++) {
        int k0 = kc * 16 + 2 * tg;
        split2(*reinterpret_cast<const float2*>(hr0 + k0),     ah[kc][0], al[kc][0]);
        split2(*reinterpret_cast<const float2*>(hr8 + k0),     ah[kc][1], al[kc][1]);
        split2(*reinterpret_cast<const float2*>(hr0 + k0 + 8), ah[kc][2], al[kc][2]);
        split2(*reinterpret_cast<const float2*>(hr8 + k0 + 8), ah[kc][3], al[kc][3]);
    }

    const uint32_t* WH = reinterpret_cast<const uint32_t*>(g_w2h);
    const uint32_t* WL = reinterpret_cast<const uint32_t*>(g_w2l);
    float acc[5][4];
    #pragma unroll
    for (int nt = 0; nt < 5; nt++)
        acc[nt][0] = acc[nt][1] = acc[nt][2] = acc[nt][3] = 0.f;
    #pragma unroll
    for (int kc = 0; kc < 8; kc++) {
        #pragma unroll
        for (int nt = 0; nt < 5; nt++) {
            int nrow = nh * 40 + nt * 8 + g;
            int idx = nrow * 64 + kc * 8 + tg;
            uint32_t bh0 = __ldg(&WH[idx]);
            uint32_t bh1 = __ldg(&WH[idx + 4]);
            uint32_t bl0 = __ldg(&WL[idx]);
            uint32_t bl1 = __ldg(&WL[idx + 4]);
            MMA_BF16(acc[nt], ah[kc], bh0, bh1);
            MMA_BF16(acc[nt], al[kc], bh0, bh1);
            MMA_BF16(acc[nt], ah[kc], bl0, bl1);
        }
    }
    float* dst = nh ? g_xr2 : g_xl2;
    #pragma unroll
    for (int nt = 0; nt < 5; nt++) {
        int col = nt * 8 + 2 * tg;   // 0..39
        if (rowg < nend)
            *reinterpret_cast<float2*>(dst + (size_t)rowg * CLS + col) =
                make_float2(acc[nt][0], acc[nt][1]);
        if (rowg8 < nend)
            *reinterpret_cast<float2*>(dst + (size_t)rowg8 * CLS + col) =
                make_float2(acc[nt][2], acc[nt][3]);
    }
}

// ---------------- fused node kernel, layer 1 (depth-4, 2-wide) ----------
__global__ void node1_kernel(const float* __restrict__ a1,
                             const float* __restrict__ b1,
                             int nbeg, int nend) {
    int n = nbeg + ((blockIdx.x * blockDim.x + threadIdx.x) >> 5);
    int lane = threadIdx.x & 31;
    if (n >= nend) return;
    int f0 = lane * 4;
    const float4 xr4 = *reinterpret_cast<const float4*>(&g_xr1[(size_t)n * D1 + f0]);
    const float4 a4  = __ldg(reinterpret_cast<const float4*>(&a1[f0]));
    int beg = g_rowptr[n];
    int cnt = g_rowptr[n + 1] - beg;
    const int* cs = g_csrc + beg;

    float den0 = 0.f, den1 = 0.f;
    float ax = 0.f, ay = 0.f, az = 0.f, aw = 0.f;

    int idx0 = cs[0];
    int idx1 = (1 < cnt) ? cs[1] : 0;
    int idx2 = (2 < cnt) ? cs[2] : 0;
    int idx3 = (3 < cnt) ? cs[3] : 0;
    float4 x0 = *reinterpret_cast<const float4*>(&g_xl1[(size_t)idx0 * D1 + f0]);
    float4 x1 = *reinterpret_cast<const float4*>(&g_xl1[(size_t)idx1 * D1 + f0]);
    float4 x2 = *reinterpret_cast<const float4*>(&g_xl1[(size_t)idx2 * D1 + f0]);
    float4 x3 = *reinterpret_cast<const float4*>(&g_xl1[(size_t)idx3 * D1 + f0]);

    int j = 0;
    for (; j + 1 < cnt; j += 2) {
        int i4 = (j + 4 < cnt) ? cs[j + 4] : 0;
        int i5 = (j + 5 < cnt) ? cs[j + 5] : 0;
        const float4 nx0 = *reinterpret_cast<const float4*>(&g_xl1[(size_t)i4 * D1 + f0]);
        const float4 nx1 = *reinterpret_cast<const float4*>(&g_xl1[(size_t)i5 * D1 + f0]);

        float s0 = lrelu(x0.x + xr4.x) * a4.x
                 + lrelu(x0.y + xr4.y) * a4.y
                 + lrelu(x0.z + xr4.z) * a4.z
                 + lrelu(x0.w + xr4.w) * a4.w;
        float s1 = lrelu(x1.x + xr4.x) * a4.x
                 + lrelu(x1.y + xr4.y) * a4.y
                 + lrelu(x1.z + xr4.z) * a4.z
                 + lrelu(x1.w + xr4.w) * a4.w;
        s0 += __shfl_xor_sync(0xffffffffu, s0, 1);
        s1 += __shfl_xor_sync(0xffffffffu, s1, 1);
        s0 += __shfl_xor_sync(0xffffffffu, s0, 2);
        s1 += __shfl_xor_sync(0xffffffffu, s1, 2);
        s0 += __shfl_xor_sync(0xffffffffu, s0, 4);
        s1 += __shfl_xor_sync(0xffffffffu, s1, 4);
        float p0 = __expf(s0);
        float p1 = __expf(s1);
        den0 += p0; den1 += p1;
        ax = fmaf(p0, x0.x, ax); ay = fmaf(p0, x0.y, ay);
        az = fmaf(p0, x0.z, az); aw = fmaf(p0, x0.w, aw);
        ax = fmaf(p1, x1.x, ax); ay = fmaf(p1, x1.y, ay);
        az = fmaf(p1, x1.z, az); aw = fmaf(p1, x1.w, aw);
        x0 = x2; x1 = x3; x2 = nx0; x3 = nx1;
    }
    if (j < cnt) {
        float s0 = lrelu(x0.x + xr4.x) * a4.x
                 + lrelu(x0.y + xr4.y) * a4.y
                 + lrelu(x0.z + xr4.z) * a4.z
                 + lrelu(x0.w + xr4.w) * a4.w;
        s0 += __shfl_xor_sync(0xffffffffu, s0, 1);
        s0 += __shfl_xor_sync(0xffffffffu, s0, 2);
        s0 += __shfl_xor_sync(0xffffffffu, s0, 4);
        float p0 = __expf(s0);
        den0 += p0;
        ax = fmaf(p0, x0.x, ax); ay = fmaf(p0, x0.y, ay);
        az = fmaf(p0, x0.z, az); aw = fmaf(p0, x0.w, aw);
    }
    float inv = 1.f / (den0 + den1);
    const float4 b4 = __ldg(reinterpret_cast<const float4*>(&b1[f0]));
    float4 o;
    o.x = ax * inv + b4.x; o.x = (o.x > 0.f) ? o.x : (__expf(o.x) - 1.f);
    o.y = ay * inv + b4.y; o.y = (o.y > 0.f) ? o.y : (__expf(o.y) - 1.f);
    o.z = az * inv + b4.z; o.z = (o.z > 0.f) ? o.z : (__expf(o.z) - 1.f);
    o.w = aw * inv + b4.w; o.w = (o.w > 0.f) ? o.w : (__expf(o.w) - 1.f);
    *reinterpret_cast<float4*>(&g_h[(size_t)n * D1 + f0]) = o;
}

// ---------------- fused node kernel, layer 2 + log_softmax (depth-4) ----
__global__ void node2_kernel(const float* __restrict__ a2,
                             const float* __restrict__ b2,
                             float* __restrict__ out) {
    int n = (blockIdx.x * blockDim.x + threadIdx.x) >> 5;
    int lane = threadIdx.x & 31;
    if (n >= NN) return;
    bool act = (lane * 2) < CLS;
    int f0 = lane * 2;
    float2 xr2v = make_float2(0.f, 0.f), a2v = make_float2(0.f, 0.f);
    if (act) {
        xr2v = *reinterpret_cast<const float2*>(&g_xr2[(size_t)n * CLS + f0]);
        a2v  = __ldg(reinterpret_cast<const float2*>(&a2[f0]));
    }
    int beg = g_rowptr[n];
    int cnt = g_rowptr[n + 1] - beg;
    const int* cs = g_csrc + beg;

    float den0 = 0.f, den1 = 0.f, ax = 0.f, ay = 0.f;
    float2 zero2 = make_float2(0.f, 0.f);

    int idx0 = cs[0];
    int idx1 = (1 < cnt) ? cs[1] : 0;
    int idx2 = (2 < cnt) ? cs[2] : 0;
    int idx3 = (3 < cnt) ? cs[3] : 0;
    float2 x0 = act ? *reinterpret_cast<const float2*>(&g_xl2[(size_t)idx0 * CLS + f0]) : zero2;
    float2 x1 = act ? *reinterpret_cast<const float2*>(&g_xl2[(size_t)idx1 * CLS + f0]) : zero2;
    float2 x2 = act ? *reinterpret_cast<const float2*>(&g_xl2[(size_t)idx2 * CLS + f0]) : zero2;
    float2 x3 = act ? *reinterpret_cast<const float2*>(&g_xl2[(size_t)idx3 * CLS + f0]) : zero2;

    int j = 0;
    for (; j + 1 < cnt; j += 2) {
        int i4 = (j + 4 < cnt) ? cs[j + 4] : 0;
        int i5 = (j + 5 < cnt) ? cs[j + 5] : 0;
        const float2 nx0 = act ? *reinterpret_cast<const float2*>(&g_xl2[(size_t)i4 * CLS + f0]) : zero2;
        const float2 nx1 = act ? *reinterpret_cast<const float2*>(&g_xl2[(size_t)i5 * CLS + f0]) : zero2;

        float s0 = lrelu(x0.x + xr2v.x) * a2v.x + lrelu(x0.y + xr2v.y) * a2v.y;
        float s1 = lrelu(x1.x + xr2v.x) * a2v.x + lrelu(x1.y + xr2v.y) * a2v.y;
        #pragma unroll
        for (int off = 16; off > 0; off >>= 1) {
            s0 += __shfl_xor_sync(0xffffffffu, s0, off);
            s1 += __shfl_xor_sync(0xffffffffu, s1, off);
        }
        float p0 = __expf(s0);
        float p1 = __expf(s1);
        den0 += p0; den1 += p1;
        ax = fmaf(p0, x0.x, ax); ay = fmaf(p0, x0.y, ay);
        ax = fmaf(p1, x1.x, ax); ay = fmaf(p1, x1.y, ay);
        x0 = x2; x1 = x3; x2 = nx0; x3 = nx1;
    }
    if (j < cnt) {
        float s0 = lrelu(x0.x + xr2v.x) * a2v.x + lrelu(x0.y + xr2v.y) * a2v.y;
        #pragma unroll
        for (int off = 16; off > 0; off >>= 1)
            s0 += __shfl_xor_sync(0xffffffffu, s0, off);
        float p0 = __expf(s0);
        den0 += p0;
        ax = fmaf(p0, x0.x, ax); ay = fmaf(p0, x0.y, ay);
    }
    float inv = 1.f / (den0 + den1);
    float v0 = -CUDART_INF_F, v1 = -CUDART_INF_F;
    if (act) {
        v0 = ax * inv + __ldg(&b2[f0]);
        v1 = ay * inv + __ldg(&b2[f0 + 1]);
    }
    float mx = fmaxf(v0, v1);
    #pragma unroll
    for (int off = 16; off > 0; off >>= 1)
        mx = fmaxf(mx, __shfl_xor_sync(0xffffffffu, mx, off));
    float se = act ? (__expf(v0 - mx) + __expf(v1 - mx)) : 0.f;
    #pragma unroll
    for (int off = 16; off > 0; off >>= 1)
        se += __shfl_xor_sync(0xffffffffu, se, off);
    float lse = mx + logf(se);
    if (act) {
        float2 o = make_float2(v0 - lse, v1 - lse);
        *reinterpret_cast<float2*>(&out[(size_t)n * CLS + f0]) = o;
    }
}

// ---------------- stream/event objects (created at process start) -------
static cudaStream_t s_side;
static cudaEvent_t  s_ev_fork;
static cudaEvent_t  s_ev_join;
static cudaEvent_t  s_ev_h;
static cudaEvent_t  s_ev_g2a;
namespace {
struct StreamInit {
    StreamInit() {
        cudaStreamCreateWithFlags(&s_side, cudaStreamNonBlocking);
        cudaEventCreateWithFlags(&s_ev_fork, cudaEventDisableTiming);
        cudaEventCreateWithFlags(&s_ev_join, cudaEventDisableTiming);
        cudaEventCreateWithFlags(&s_ev_h, cudaEventDisableTiming);
        cudaEventCreateWithFlags(&s_ev_g2a, cudaEventDisableTiming);
    }
};
static StreamInit s_stream_init;
}

// ---------------- launch ----------------
extern "C" void kernel_launch(void* const* d_in, const int* in_sizes, int n_in,
                              void* d_out, int out_size) {
    const float* x    = (const float*)d_in[0];
    const int*   eiw  = (const int*)d_in[1];
    const float* w1_l = (const float*)d_in[2];
    const float* w1_r = (const float*)d_in[3];
    const float* a1   = (const float*)d_in[4];
    const float* b1   = (const float*)d_in[5];
    const float* w2_l = (const float*)d_in[6];
    const float* w2_r = (const float*)d_in[7];
    const float* a2   = (const float*)d_in[8];
    const float* b2   = (const float*)d_in[9];
    float*       out  = (float*)d_out;

    // fork: CSR build on side stream, weight prep + gemm1 on main stream
    cudaEventRecord(s_ev_fork, 0);
    cudaStreamWaitEvent(s_side, s_ev_fork, 0);

    conv_hist_kernel<<<(ET + 255) / 256, 256, 0, s_side>>>(eiw);
    scan1_kernel<<<NBLK, SCANB, 0, s_side>>>();
    scan3_kernel<<<(NN + 255) / 256, 256, 0, s_side>>>();
    scatter_kernel<<<(ET + 255) / 256, 256, 0, s_side>>>();
    cudaEventRecord(s_ev_join, s_side);

    wprep_kernel<<<(128 * 128 + 80 * 128 + 255) / 256, 256>>>(w1_l, w1_r, w2_l, w2_r);
    gemm1_mma_kernel<<<(NN + 63) / 64, 256>>>(x);

    // join CSR
    cudaStreamWaitEvent(0, s_ev_join, 0);

    node1_kernel<<<(NHALF * 32) / 256, 256>>>(a1, b1, 0, NHALF);
    cudaEventRecord(s_ev_h, 0);
    cudaStreamWaitEvent(s_side, s_ev_h, 0);
    gemm2_mma_kernel<<<NHALF / 64, 256, 0, s_side>>>(0, NHALF);
    cudaEventRecord(s_ev_g2a, s_side);

    node1_kernel<<<((NN - NHALF) * 32 + 255) / 256, 256>>>(a1, b1, NHALF, NN);
    gemm2_mma_kernel<<<(NN - NHALF + 63) / 64, 256>>>(NHALF, NN);

    cudaStreamWaitEvent(0, s_ev_g2a, 0);
    node2_kernel<<<(NN * 32 + 255) / 256, 256>>>(a2, b2, out);
}

// round 13
// speedup vs baseline: 1.4675x; 1.4675x over previous
#include <cuda_runtime.h>
#include <cuda_bf16.h>
#include <math.h>
#include <math_constants.h>
#include <cstdint>

// Problem constants (fixed shapes per reference)
#define NN    50000                // nodes
#define NE    800000               // edges (without self loops)
#define ET    (NE + NN)            // edges + self loops
#define D1    128                  // HEADS*CH  (also F_IN)
#define HEADS 4
#define CH    32
#define CLS   40
#define SCANB 1024
#define NBLK  ((NN + SCANB - 1) / SCANB)   // 49
#define NHALF 25600                // node1/gemm2 pipeline split (mult of 128)

typedef unsigned long long ull;

// ---------------- scratch (static device allocations) ----------------
static __device__ float g_xl1[(size_t)NN * D1];
static __device__ float g_xr1[(size_t)NN * D1];
static __device__ float g_h  [(size_t)NN * D1];
static __device__ float g_xl2[(size_t)NN * CLS];
static __device__ float g_xr2[(size_t)NN * CLS];
static __device__ int   g_deg[NN];          // zeroed in scan3 (BSS-zero first run)
static __device__ int   g_incl[NBLK * SCANB];
static __device__ int   g_bsum[NBLK];
static __device__ int   g_rowptr[NN + 1];
static __device__ int   g_cursor[NN];
static __device__ int   g_csrc[ET];
// split-bf16 weight tiles, [n][k] layout (n = output col, k contiguous)
static __device__ __nv_bfloat16 g_wlh[128 * 128];
static __device__ __nv_bfloat16 g_wll[128 * 128];
static __device__ __nv_bfloat16 g_wrh[128 * 128];
static __device__ __nv_bfloat16 g_wrl[128 * 128];
static __device__ __nv_bfloat16 g_w2h[80 * 128];   // layer2 stacked [l|r]
static __device__ __nv_bfloat16 g_w2l[80 * 128];

// ---------------- helpers ----------------
__device__ __forceinline__ float lrelu(float v) {
    return (v > 0.f) ? v : 0.2f * v;
}

#define MMA_BF16(d, a, b0, b1)                                                 \
    asm volatile("mma.sync.aligned.m16n8k16.row.col.f32.bf16.bf16.f32 "        \
        "{%0,%1,%2,%3}, {%4,%5,%6,%7}, {%8,%9}, {%0,%1,%2,%3};"                \
        : "+f"((d)[0]), "+f"((d)[1]), "+f"((d)[2]), "+f"((d)[3])               \
        : "r"((a)[0]), "r"((a)[1]), "r"((a)[2]), "r"((a)[3]), "r"(b0), "r"(b1))

__device__ __forceinline__ void split2(float2 p, uint32_t& hi, uint32_t& lo) {
    __nv_bfloat16 hx = __float2bfloat16(p.x);
    __nv_bfloat16 hy = __float2bfloat16(p.y);
    __nv_bfloat16 lx = __float2bfloat16(p.x - __bfloat162float(hx));
    __nv_bfloat16 ly = __float2bfloat16(p.y - __bfloat162float(hy));
    __nv_bfloat162 h2(hx, hy), l2(lx, ly);
    hi = *reinterpret_cast<uint32_t*>(&h2);
    lo = *reinterpret_cast<uint32_t*>(&l2);
}
__device__ __forceinline__ void splitw(float v, __nv_bfloat16* ph, __nv_bfloat16* pl) {
    __nv_bfloat16 h = __float2bfloat16(v);
    *ph = h;
    *pl = __float2bfloat16(v - __bfloat162float(h));
}

// per-block int64-vs-int32 detection (odd words all zero => int64)
__device__ __forceinline__ int detect_is64(const int* __restrict__ w) {
    int nz = 0;
    for (int k = threadIdx.x; k < 64; k += blockDim.x)
        nz |= (w[2 * k + 1] != 0);
    return __syncthreads_or(nz) ? 0 : 1;
}

// ---------------- CSR build (4 kernels, no src/dst staging) -------------
__global__ void hist_kernel(const int* __restrict__ w) {
    int is64 = detect_is64(w);
    int e = blockIdx.x * blockDim.x + threadIdx.x;
    if (e >= ET) return;
    int dst;
    if (e >= NE)      dst = e - NE;
    else if (is64)    dst = w[2 * (NE + e)];
    else              dst = w[NE + e];
    atomicAdd(&g_deg[dst], 1);
}

__global__ void scan1_kernel() {
    __shared__ int sm[SCANB];
    int t = threadIdx.x;
    int i = blockIdx.x * SCANB + t;
    sm[t] = (i < NN) ? g_deg[i] : 0;
    __syncthreads();
    for (int off = 1; off < SCANB; off <<= 1) {
        int add = (t >= off) ? sm[t - off] : 0;
        __syncthreads();
        sm[t] += add;
        __syncthreads();
    }
    g_incl[i] = sm[t];
    if (t == SCANB - 1) g_bsum[blockIdx.x] = sm[t];
}

// scan3 with scan2 fused: every block locally scans the 49 block sums
__global__ void scan3_kernel() {
    __shared__ int sb[64];
    int t = threadIdx.x;
    if (t < 64) sb[t] = (t < NBLK) ? g_bsum[t] : 0;
    __syncthreads();
    for (int off = 1; off < 64; off <<= 1) {
        int add = (t < 64 && t >= off) ? sb[t - off] : 0;
        __syncthreads();
        if (t < 64) sb[t] += add;
        __syncthreads();
    }
    int i = blockIdx.x * blockDim.x + t;
    if (i >= NN) return;
    int b = i >> 10;
    int boff = (b == 0) ? 0 : sb[b - 1];
    int incl = g_incl[i] + boff;
    g_rowptr[i + 1] = incl;
    g_cursor[i] = incl - g_deg[i];
    g_deg[i] = 0;              // reset for next replay
    if (i == 0) g_rowptr[0] = 0;
}

__global__ void scatter_kernel(const int* __restrict__ w) {
    int is64 = detect_is64(w);
    int e = blockIdx.x * blockDim.x + threadIdx.x;
    if (e >= ET) return;
    int src, dst;
    if (e >= NE) {
        src = e - NE; dst = src;
    } else if (is64) {
        src = w[2 * e];
        dst = w[2 * (NE + e)];
    } else {
        src = w[e];
        dst = w[NE + e];
    }
    int pos = atomicAdd(&g_cursor[dst], 1);
    g_csrc[pos] = src;
}

// ---------------- weight prep: both layers, split bf16 [n][k] -----------
__global__ void wprep_kernel(const float* __restrict__ wl1,
                             const float* __restrict__ wr1,
                             const float* __restrict__ wl2,
                             const float* __restrict__ wr2) {
    int i = blockIdx.x * blockDim.x + threadIdx.x;
    if (i < 128 * 128) {
        int k = i >> 7, n = i & 127;
        int o = n * 128 + k;
        splitw(wl1[i], &g_wlh[o], &g_wll[o]);
        splitw(wr1[i], &g_wrh[o], &g_wrl[o]);
    } else if (i < 128 * 128 + 80 * 128) {
        int j = i - 128 * 128;
        int n = j >> 7, k = j & 127;
        float v = (n < CLS) ? wl2[k * CLS + n] : wr2[k * CLS + (n - CLS)];
        splitw(v, &g_w2h[j], &g_w2l[j]);
    }
}

// ---------------- layer 1 GEMM via mma.sync bf16 (split, fp32 accum) ----
#define BROW_BYTES 272        // 136 bf16; conflict-free frag loads
#define BTILE_BYTES (128 * BROW_BYTES)
#define G1_SMEM (4 * BTILE_BYTES)

__global__ __launch_bounds__(512) void gemm1_mma_kernel(const float* __restrict__ x) {
    extern __shared__ char smc[];
    {
        const __nv_bfloat16* gsrc[4] = {g_wlh, g_wll, g_wrh, g_wrl};
        #pragma unroll
        for (int tsel = 0; tsel < 4; tsel++) {
            const uint4* s = reinterpret_cast<const uint4*>(gsrc[tsel]);
            char* d = smc + tsel * BTILE_BYTES;
            for (int j = threadIdx.x; j < 128 * 16; j += 512) {
                int row = j >> 4, q = j & 15;
                *reinterpret_cast<uint4*>(d + row * BROW_BYTES + q * 16) = s[j];
            }
        }
    }
    int lane = threadIdx.x & 31, wid = threadIdx.x >> 5;
    int g = lane >> 2, tg = lane & 3;
    int mw = wid & 7, nh = wid >> 3;
    int rowg  = blockIdx.x * 128 + mw * 16 + g;
    int rowg8 = rowg + 8;
    int r0 = (rowg  < NN) ? rowg  : (NN - 1);
    int r8 = (rowg8 < NN) ? rowg8 : (NN - 1);
    const float* xr0 = x + (size_t)r0 * D1;
    const float* xr8 = x + (size_t)r8 * D1;

    uint32_t ah[8][4], al[8][4];
    #pragma unroll
    for (int kc = 0; kc < 8; kc++) {
        int k0 = kc * 16 + 2 * tg;
        split2(*reinterpret_cast<const float2*>(xr0 + k0),     ah[kc][0], al[kc][0]);
        split2(*reinterpret_cast<const float2*>(xr8 + k0),     ah[kc][1], al[kc][1]);
        split2(*reinterpret_cast<const float2*>(xr0 + k0 + 8), ah[kc][2], al[kc][2]);
        split2(*reinterpret_cast<const float2*>(xr8 + k0 + 8), ah[kc][3], al[kc][3]);
    }
    __syncthreads();

    #pragma unroll
    for (int wsel = 0; wsel < 2; wsel++) {
        const char* BH = smc + (wsel * 2 + 0) * BTILE_BYTES;
        const char* BL = smc + (wsel * 2 + 1) * BTILE_BYTES;
        float acc[8][4];
        #pragma unroll
        for (int nt = 0; nt < 8; nt++)
            acc[nt][0] = acc[nt][1] = acc[nt][2] = acc[nt][3] = 0.f;
        #pragma unroll
        for (int kc = 0; kc < 8; kc++) {
            int kb = kc * 32 + tg * 4;
            #pragma unroll
            for (int nt = 0; nt < 8; nt++) {
                int nrow = nh * 64 + nt * 8 + g;
                const char* ph = BH + nrow * BROW_BYTES + kb;
                const char* pl = BL + nrow * BROW_BYTES + kb;
                uint32_t bh0 = *reinterpret_cast<const uint32_t*>(ph);
                uint32_t bh1 = *reinterpret_cast<const uint32_t*>(ph + 16);
                uint32_t bl0 = *reinterpret_cast<const uint32_t*>(pl);
                uint32_t bl1 = *reinterpret_cast<const uint32_t*>(pl + 16);
                MMA_BF16(acc[nt], ah[kc], bh0, bh1);
                MMA_BF16(acc[nt], al[kc], bh0, bh1);
                MMA_BF16(acc[nt], ah[kc], bl0, bl1);
            }
        }
        float* dst = wsel ? g_xr1 : g_xl1;
        #pragma unroll
        for (int nt = 0; nt < 8; nt++) {
            int col = nh * 64 + nt * 8 + 2 * tg;
            if (rowg < NN)
                *reinterpret_cast<float2*>(dst + (size_t)rowg * D1 + col) =
                    make_float2(acc[nt][0], acc[nt][1]);
            if (rowg8 < NN)
                *reinterpret_cast<float2*>(dst + (size_t)rowg8 * D1 + col) =
                    make_float2(acc[nt][2], acc[nt][3]);
        }
    }
}

// ---------------- layer 2 GEMM via mma.sync (N=80 stacked) --------------
#define B2TILE (80 * BROW_BYTES)
#define G2_SMEM (2 * B2TILE)

__global__ __launch_bounds__(512) void gemm2_mma_kernel(int nbeg, int nend) {
    extern __shared__ char smc[];
    {
        const __nv_bfloat16* gsrc[2] = {g_w2h, g_w2l};
        #pragma unroll
        for (int tsel = 0; tsel < 2; tsel++) {
            const uint4* s = reinterpret_cast<const uint4*>(gsrc[tsel]);
            char* d = smc + tsel * B2TILE;
            for (int j = threadIdx.x; j < 80 * 16; j += 512) {
                int row = j >> 4, q = j & 15;
                *reinterpret_cast<uint4*>(d + row * BROW_BYTES + q * 16) = s[j];
            }
        }
    }
    int lane = threadIdx.x & 31, wid = threadIdx.x >> 5;
    int g = lane >> 2, tg = lane & 3;
    int mw = wid & 7, nh = wid >> 3;
    int rowg  = nbeg + blockIdx.x * 128 + mw * 16 + g;
    int rowg8 = rowg + 8;
    int r0 = (rowg  < NN) ? rowg  : (NN - 1);
    int r8 = (rowg8 < NN) ? rowg8 : (NN - 1);
    const float* hr0 = g_h + (size_t)r0 * D1;
    const float* hr8 = g_h + (size_t)r8 * D1;

    uint32_t ah[8][4], al[8][4];
    #pragma unroll
    for (int kc = 0; kc < 8; kc++) {
        int k0 = kc * 16 + 2 * tg;
        split2(*reinterpret_cast<const float2*>(hr0 + k0),     ah[kc][0], al[kc][0]);
        split2(*reinterpret_cast<const float2*>(hr8 + k0),     ah[kc][1], al[kc][1]);
        split2(*reinterpret_cast<const float2*>(hr0 + k0 + 8), ah[kc][2], al[kc][2]);
        split2(*reinterpret_cast<const float2*>(hr8 + k0 + 8), ah[kc][3], al[kc][3]);
    }
    __syncthreads();

    float acc[5][4];
    #pragma unroll
    for (int nt = 0; nt < 5; nt++)
        acc[nt][0] = acc[nt][1] = acc[nt][2] = acc[nt][3] = 0.f;
    #pragma unroll
    for (int kc = 0; kc < 8; kc++) {
        int kb = kc * 32 + tg * 4;
        #pragma unroll
        for (int nt = 0; nt < 5; nt++) {
            int nrow = nh * 40 + nt * 8 + g;
            const char* ph = smc + nrow * BROW_BYTES + kb;
            const char* pl = ph + B2TILE;
            uint32_t bh0 = *reinterpret_cast<const uint32_t*>(ph);
            uint32_t bh1 = *reinterpret_cast<const uint32_t*>(ph + 16);
            uint32_t bl0 = *reinterpret_cast<const uint32_t*>(pl);
            uint32_t bl1 = *reinterpret_cast<const uint32_t*>(pl + 16);
            MMA_BF16(acc[nt], ah[kc], bh0, bh1);
            MMA_BF16(acc[nt], al[kc], bh0, bh1);
            MMA_BF16(acc[nt], ah[kc], bl0, bl1);
        }
    }
    float* dst = nh ? g_xr2 : g_xl2;
    #pragma unroll
    for (int nt = 0; nt < 5; nt++) {
        int col = nt * 8 + 2 * tg;   // 0..39
        if (rowg < nend)
            *reinterpret_cast<float2*>(dst + (size_t)rowg * CLS + col) =
                make_float2(acc[nt][0], acc[nt][1]);
        if (rowg8 < nend)
            *reinterpret_cast<float2*>(dst + (size_t)rowg8 * CLS + col) =
                make_float2(acc[nt][2], acc[nt][3]);
    }
}

// ---------------- fused node kernel, layer 1 (depth-4, 2-wide) ----------
__global__ void node1_kernel(const float* __restrict__ a1,
                             const float* __restrict__ b1,
                             int nbeg, int nend) {
    int n = nbeg + ((blockIdx.x * blockDim.x + threadIdx.x) >> 5);
    int lane = threadIdx.x & 31;
    if (n >= nend) return;
    int f0 = lane * 4;
    const float4 xr4 = *reinterpret_cast<const float4*>(&g_xr1[(size_t)n * D1 + f0]);
    const float4 a4  = __ldg(reinterpret_cast<const float4*>(&a1[f0]));
    int beg = g_rowptr[n];
    int cnt = g_rowptr[n + 1] - beg;
    const int* cs = g_csrc + beg;

    float den0 = 0.f, den1 = 0.f;
    float ax = 0.f, ay = 0.f, az = 0.f, aw = 0.f;

    int idx0 = cs[0];
    int idx1 = (1 < cnt) ? cs[1] : 0;
    int idx2 = (2 < cnt) ? cs[2] : 0;
    int idx3 = (3 < cnt) ? cs[3] : 0;
    float4 x0 = *reinterpret_cast<const float4*>(&g_xl1[(size_t)idx0 * D1 + f0]);
    float4 x1 = *reinterpret_cast<const float4*>(&g_xl1[(size_t)idx1 * D1 + f0]);
    float4 x2 = *reinterpret_cast<const float4*>(&g_xl1[(size_t)idx2 * D1 + f0]);
    float4 x3 = *reinterpret_cast<const float4*>(&g_xl1[(size_t)idx3 * D1 + f0]);

    int j = 0;
    for (; j + 1 < cnt; j += 2) {
        int i4 = (j + 4 < cnt) ? cs[j + 4] : 0;
        int i5 = (j + 5 < cnt) ? cs[j + 5] : 0;
        const float4 nx0 = *reinterpret_cast<const float4*>(&g_xl1[(size_t)i4 * D1 + f0]);
        const float4 nx1 = *reinterpret_cast<const float4*>(&g_xl1[(size_t)i5 * D1 + f0]);

        float s0 = lrelu(x0.x + xr4.x) * a4.x
                 + lrelu(x0.y + xr4.y) * a4.y
                 + lrelu(x0.z + xr4.z) * a4.z
                 + lrelu(x0.w + xr4.w) * a4.w;
        float s1 = lrelu(x1.x + xr4.x) * a4.x
                 + lrelu(x1.y + xr4.y) * a4.y
                 + lrelu(x1.z + xr4.z) * a4.z
                 + lrelu(x1.w + xr4.w) * a4.w;
        s0 += __shfl_xor_sync(0xffffffffu, s0, 1);
        s1 += __shfl_xor_sync(0xffffffffu, s1, 1);
        s0 += __shfl_xor_sync(0xffffffffu, s0, 2);
        s1 += __shfl_xor_sync(0xffffffffu, s1, 2);
        s0 += __shfl_xor_sync(0xffffffffu, s0, 4);
        s1 += __shfl_xor_sync(0xffffffffu, s1, 4);
        float p0 = __expf(s0);
        float p1 = __expf(s1);
        den0 += p0; den1 += p1;
        ax = fmaf(p0, x0.x, ax); ay = fmaf(p0, x0.y, ay);
        az = fmaf(p0, x0.z, az); aw = fmaf(p0, x0.w, aw);
        ax = fmaf(p1, x1.x, ax); ay = fmaf(p1, x1.y, ay);
        az = fmaf(p1, x1.z, az); aw = fmaf(p1, x1.w, aw);
        x0 = x2; x1 = x3; x2 = nx0; x3 = nx1;
    }
    if (j < cnt) {
        float s0 = lrelu(x0.x + xr4.x) * a4.x
                 + lrelu(x0.y + xr4.y) * a4.y
                 + lrelu(x0.z + xr4.z) * a4.z
                 + lrelu(x0.w + xr4.w) * a4.w;
        s0 += __shfl_xor_sync(0xffffffffu, s0, 1);
        s0 += __shfl_xor_sync(0xffffffffu, s0, 2);
        s0 += __shfl_xor_sync(0xffffffffu, s0, 4);
        float p0 = __expf(s0);
        den0 += p0;
        ax = fmaf(p0, x0.x, ax); ay = fmaf(p0, x0.y, ay);
        az = fmaf(p0, x0.z, az); aw = fmaf(p0, x0.w, aw);
    }
    float inv = 1.f / (den0 + den1);
    const float4 b4 = __ldg(reinterpret_cast<const float4*>(&b1[f0]));
    float4 o;
    o.x = ax * inv + b4.x; o.x = (o.x > 0.f) ? o.x : (__expf(o.x) - 1.f);
    o.y = ay * inv + b4.y; o.y = (o.y > 0.f) ? o.y : (__expf(o.y) - 1.f);
    o.z = az * inv + b4.z; o.z = (o.z > 0.f) ? o.z : (__expf(o.z) - 1.f);
    o.w = aw * inv + b4.w; o.w = (o.w > 0.f) ? o.w : (__expf(o.w) - 1.f);
    *reinterpret_cast<float4*>(&g_h[(size_t)n * D1 + f0]) = o;
}

// ---------------- fused node kernel, layer 2 + log_softmax (depth-4) ----
__global__ void node2_kernel(const float* __restrict__ a2,
                             const float* __restrict__ b2,
                             float* __restrict__ out) {
    int n = (blockIdx.x * blockDim.x + threadIdx.x) >> 5;
    int lane = threadIdx.x & 31;
    if (n >= NN) return;
    bool act = (lane * 2) < CLS;
    int f0 = lane * 2;
    float2 xr2v = make_float2(0.f, 0.f), a2v = make_float2(0.f, 0.f);
    if (act) {
        xr2v = *reinterpret_cast<const float2*>(&g_xr2[(size_t)n * CLS + f0]);
        a2v  = __ldg(reinterpret_cast<const float2*>(&a2[f0]));
    }
    int beg = g_rowptr[n];
    int cnt = g_rowptr[n + 1] - beg;
    const int* cs = g_csrc + beg;

    float den0 = 0.f, den1 = 0.f, ax = 0.f, ay = 0.f;
    float2 zero2 = make_float2(0.f, 0.f);

    int idx0 = cs[0];
    int idx1 = (1 < cnt) ? cs[1] : 0;
    int idx2 = (2 < cnt) ? cs[2] : 0;
    int idx3 = (3 < cnt) ? cs[3] : 0;
    float2 x0 = act ? *reinterpret_cast<const float2*>(&g_xl2[(size_t)idx0 * CLS + f0]) : zero2;
    float2 x1 = act ? *reinterpret_cast<const float2*>(&g_xl2[(size_t)idx1 * CLS + f0]) : zero2;
    float2 x2 = act ? *reinterpret_cast<const float2*>(&g_xl2[(size_t)idx2 * CLS + f0]) : zero2;
    float2 x3 = act ? *reinterpret_cast<const float2*>(&g_xl2[(size_t)idx3 * CLS + f0]) : zero2;

    int j = 0;
    for (; j + 1 < cnt; j += 2) {
        int i4 = (j + 4 < cnt) ? cs[j + 4] : 0;
        int i5 = (j + 5 < cnt) ? cs[j + 5] : 0;
        const float2 nx0 = act ? *reinterpret_cast<const float2*>(&g_xl2[(size_t)i4 * CLS + f0]) : zero2;
        const float2 nx1 = act ? *reinterpret_cast<const float2*>(&g_xl2[(size_t)i5 * CLS + f0]) : zero2;

        float s0 = lrelu(x0.x + xr2v.x) * a2v.x + lrelu(x0.y + xr2v.y) * a2v.y;
        float s1 = lrelu(x1.x + xr2v.x) * a2v.x + lrelu(x1.y + xr2v.y) * a2v.y;
        #pragma unroll
        for (int off = 16; off > 0; off >>= 1) {
            s0 += __shfl_xor_sync(0xffffffffu, s0, off);
            s1 += __shfl_xor_sync(0xffffffffu, s1, off);
        }
        float p0 = __expf(s0);
        float p1 = __expf(s1);
        den0 += p0; den1 += p1;
        ax = fmaf(p0, x0.x, ax); ay = fmaf(p0, x0.y, ay);
        ax = fmaf(p1, x1.x, ax); ay = fmaf(p1, x1.y, ay);
        x0 = x2; x1 = x3; x2 = nx0; x3 = nx1;
    }
    if (j < cnt) {
        float s0 = lrelu(x0.x + xr2v.x) * a2v.x + lrelu(x0.y + xr2v.y) * a2v.y;
        #pragma unroll
        for (int off = 16; off > 0; off >>= 1)
            s0 += __shfl_xor_sync(0xffffffffu, s0, off);
        float p0 = __expf(s0);
        den0 += p0;
        ax = fmaf(p0, x0.x, ax); ay = fmaf(p0, x0.y, ay);
    }
    float inv = 1.f / (den0 + den1);
    float v0 = -CUDART_INF_F, v1 = -CUDART_INF_F;
    if (act) {
        v0 = ax * inv + __ldg(&b2[f0]);
        v1 = ay * inv + __ldg(&b2[f0 + 1]);
    }
    float mx = fmaxf(v0, v1);
    #pragma unroll
    for (int off = 16; off > 0; off >>= 1)
        mx = fmaxf(mx, __shfl_xor_sync(0xffffffffu, mx, off));
    float se = act ? (__expf(v0 - mx) + __expf(v1 - mx)) : 0.f;
    #pragma unroll
    for (int off = 16; off > 0; off >>= 1)
        se += __shfl_xor_sync(0xffffffffu, se, off);
    float lse = mx + logf(se);
    if (act) {
        float2 o = make_float2(v0 - lse, v1 - lse);
        *reinterpret_cast<float2*>(&out[(size_t)n * CLS + f0]) = o;
    }
}

// ---------------- stream/event objects (created at process start) -------
static cudaStream_t s_side;
static cudaEvent_t  s_ev_fork;
static cudaEvent_t  s_ev_join;
static cudaEvent_t  s_ev_h;
static cudaEvent_t  s_ev_g2a;
namespace {
struct StreamInit {
    StreamInit() {
        cudaStreamCreateWithFlags(&s_side, cudaStreamNonBlocking);
        cudaEventCreateWithFlags(&s_ev_fork, cudaEventDisableTiming);
        cudaEventCreateWithFlags(&s_ev_join, cudaEventDisableTiming);
        cudaEventCreateWithFlags(&s_ev_h, cudaEventDisableTiming);
        cudaEventCreateWithFlags(&s_ev_g2a, cudaEventDisableTiming);
        cudaFuncSetAttribute(gemm1_mma_kernel,
                             cudaFuncAttributeMaxDynamicSharedMemorySize, G1_SMEM);
        cudaFuncSetAttribute(gemm2_mma_kernel,
                             cudaFuncAttributeMaxDynamicSharedMemorySize, G2_SMEM);
    }
};
static StreamInit s_stream_init;
}

// ---------------- launch ----------------
extern "C" void kernel_launch(void* const* d_in, const int* in_sizes, int n_in,
                              void* d_out, int out_size) {
    const float* x    = (const float*)d_in[0];
    const int*   eiw  = (const int*)d_in[1];
    const float* w1_l = (const float*)d_in[2];
    const float* w1_r = (const float*)d_in[3];
    const float* a1   = (const float*)d_in[4];
    const float* b1   = (const float*)d_in[5];
    const float* w2_l = (const float*)d_in[6];
    const float* w2_r = (const float*)d_in[7];
    const float* a2   = (const float*)d_in[8];
    const float* b2   = (const float*)d_in[9];
    float*       out  = (float*)d_out;

    // fork: CSR build on side stream, weight prep + gemm1 on main stream
    cudaEventRecord(s_ev_fork, 0);
    cudaStreamWaitEvent(s_side, s_ev_fork, 0);

    hist_kernel<<<(ET + 255) / 256, 256, 0, s_side>>>(eiw);
    scan1_kernel<<<NBLK, SCANB, 0, s_side>>>();
    scan3_kernel<<<(NN + 255) / 256, 256, 0, s_side>>>();
    scatter_kernel<<<(ET + 255) / 256, 256, 0, s_side>>>(eiw);
    cudaEventRecord(s_ev_join, s_side);

    wprep_kernel<<<(128 * 128 + 80 * 128 + 255) / 256, 256>>>(w1_l, w1_r, w2_l, w2_r);
    gemm1_mma_kernel<<<(NN + 127) / 128, 512, G1_SMEM>>>(x);

    // join CSR
    cudaStreamWaitEvent(0, s_ev_join, 0);

    node1_kernel<<<(NHALF * 32) / 256, 256>>>(a1, b1, 0, NHALF);
    cudaEventRecord(s_ev_h, 0);
    cudaStreamWaitEvent(s_side, s_ev_h, 0);
    gemm2_mma_kernel<<<NHALF / 128, 512, G2_SMEM, s_side>>>(0, NHALF);
    cudaEventRecord(s_ev_g2a, s_side);

    node1_kernel<<<((NN - NHALF) * 32 + 255) / 256, 256>>>(a1, b1, NHALF, NN);
    gemm2_mma_kernel<<<(NN - NHALF + 127) / 128, 512, G2_SMEM>>>(NHALF, NN);

    cudaStreamWaitEvent(0, s_ev_g2a, 0);
    node2_kernel<<<(NN * 32 + 255) / 256, 256>>>(a2, b2, out);
}

// round 15
// speedup vs baseline: 1.5520x; 1.0576x over previous
#include <cuda_runtime.h>
#include <cuda_bf16.h>
#include <cuda_fp16.h>
#include <math.h>
#include <math_constants.h>
#include <cstdint>

// Problem constants (fixed shapes per reference)
#define NN    50000                // nodes
#define NE    800000               // edges (without self loops)
#define ET    (NE + NN)            // edges + self loops
#define D1    128                  // HEADS*CH  (also F_IN)
#define HEADS 4
#define CH    32
#define CLS   40
#define SCANB 1024
#define NBLK  ((NN + SCANB - 1) / SCANB)   // 49
#define NHALF 25600                // node1/gemm2 pipeline split (mult of 128)

typedef unsigned long long ull;

// ---------------- scratch (static device allocations) ----------------
static __device__ __half g_xl1h[(size_t)NN * D1];   // gathered operand: fp16
static __device__ float  g_xr1[(size_t)NN * D1];
static __device__ float  g_h  [(size_t)NN * D1];
static __device__ __half g_xl2h[(size_t)NN * CLS];  // gathered operand: fp16
static __device__ float  g_xr2[(size_t)NN * CLS];
static __device__ int    g_src[ET];
static __device__ int    g_dst[ET];
static __device__ int    g_deg[NN];          // zeroed in scan3 (BSS-zero first run)
static __device__ int    g_incl[NBLK * SCANB];
static __device__ int    g_bsum[NBLK];
static __device__ int    g_rowptr[NN + 1];
static __device__ int    g_cursor[NN];
static __device__ int    g_csrc[ET];
// split-bf16 weight tiles, [n][k] layout (n = output col, k contiguous)
static __device__ __nv_bfloat16 g_wlh[128 * 128];
static __device__ __nv_bfloat16 g_wll[128 * 128];
static __device__ __nv_bfloat16 g_wrh[128 * 128];
static __device__ __nv_bfloat16 g_wrl[128 * 128];
static __device__ __nv_bfloat16 g_w2h[80 * 128];   // layer2 stacked [l|r]
static __device__ __nv_bfloat16 g_w2l[80 * 128];

// ---------------- helpers ----------------
__device__ __forceinline__ float lrelu(float v) {
    return (v > 0.f) ? v : 0.2f * v;
}

#define MMA_BF16(d, a, b0, b1)                                                 \
    asm volatile("mma.sync.aligned.m16n8k16.row.col.f32.bf16.bf16.f32 "        \
        "{%0,%1,%2,%3}, {%4,%5,%6,%7}, {%8,%9}, {%0,%1,%2,%3};"                \
        : "+f"((d)[0]), "+f"((d)[1]), "+f"((d)[2]), "+f"((d)[3])               \
        : "r"((a)[0]), "r"((a)[1]), "r"((a)[2]), "r"((a)[3]), "r"(b0), "r"(b1))

__device__ __forceinline__ void split2(float2 p, uint32_t& hi, uint32_t& lo) {
    __nv_bfloat16 hx = __float2bfloat16(p.x);
    __nv_bfloat16 hy = __float2bfloat16(p.y);
    __nv_bfloat16 lx = __float2bfloat16(p.x - __bfloat162float(hx));
    __nv_bfloat16 ly = __float2bfloat16(p.y - __bfloat162float(hy));
    __nv_bfloat162 h2(hx, hy), l2(lx, ly);
    hi = *reinterpret_cast<uint32_t*>(&h2);
    lo = *reinterpret_cast<uint32_t*>(&l2);
}
__device__ __forceinline__ void splitw(float v, __nv_bfloat16* ph, __nv_bfloat16* pl) {
    __nv_bfloat16 h = __float2bfloat16(v);
    *ph = h;
    *pl = __float2bfloat16(v - __bfloat162float(h));
}
// raw fp16x4 (uint2) -> float4
__device__ __forceinline__ float4 h4_to_f4(uint2 r) {
    __half2 a = *reinterpret_cast<__half2*>(&r.x);
    __half2 b = *reinterpret_cast<__half2*>(&r.y);
    float2 fa = __half22float2(a), fb = __half22float2(b);
    return make_float4(fa.x, fa.y, fb.x, fb.y);
}
// raw fp16x2 (uint32) -> float2
__device__ __forceinline__ float2 h2_to_f2(uint32_t r) {
    __half2 a = *reinterpret_cast<__half2*>(&r);
    return __half22float2(a);
}

// ---------------- CSR build (4 kernels) ---------------------------------
// conv: detect int64 per block (64 odd-word samples) + convert + histogram
__global__ void conv_hist_kernel(const int* __restrict__ w) {
    int nz = 0;
    for (int k = threadIdx.x; k < 64; k += blockDim.x)
        nz |= (w[2 * k + 1] != 0);
    int is64 = __syncthreads_or(nz) ? 0 : 1;

    int e = blockIdx.x * blockDim.x + threadIdx.x;
    if (e >= ET) return;
    int src, dst;
    if (e >= NE) {
        src = e - NE; dst = src;
    } else if (is64) {
        src = w[2 * e];
        dst = w[2 * (NE + e)];
    } else {
        src = w[e];
        dst = w[NE + e];
    }
    g_src[e] = src;
    g_dst[e] = dst;
    atomicAdd(&g_deg[dst], 1);
}

__global__ void scan1_kernel() {
    __shared__ int sm[SCANB];
    int t = threadIdx.x;
    int i = blockIdx.x * SCANB + t;
    sm[t] = (i < NN) ? g_deg[i] : 0;
    __syncthreads();
    for (int off = 1; off < SCANB; off <<= 1) {
        int add = (t >= off) ? sm[t - off] : 0;
        __syncthreads();
        sm[t] += add;
        __syncthreads();
    }
    g_incl[i] = sm[t];
    if (t == SCANB - 1) g_bsum[blockIdx.x] = sm[t];
}

// scan3 with scan2 fused: every block locally scans the 49 block sums
__global__ void scan3_kernel() {
    __shared__ int sb[64];
    int t = threadIdx.x;
    if (t < 64) sb[t] = (t < NBLK) ? g_bsum[t] : 0;
    __syncthreads();
    for (int off = 1; off < 64; off <<= 1) {
        int add = (t < 64 && t >= off) ? sb[t - off] : 0;
        __syncthreads();
        if (t < 64) sb[t] += add;
        __syncthreads();
    }
    int i = blockIdx.x * blockDim.x + t;
    if (i >= NN) return;
    int b = i >> 10;
    int boff = (b == 0) ? 0 : sb[b - 1];
    int incl = g_incl[i] + boff;
    g_rowptr[i + 1] = incl;
    g_cursor[i] = incl - g_deg[i];
    g_deg[i] = 0;              // reset for next replay
    if (i == 0) g_rowptr[0] = 0;
}

__global__ void scatter_kernel() {
    int e = blockIdx.x * blockDim.x + threadIdx.x;
    if (e >= ET) return;
    int dst = g_dst[e];
    int pos = atomicAdd(&g_cursor[dst], 1);
    g_csrc[pos] = g_src[e];
}

// ---------------- weight prep: both layers, split bf16 [n][k] -----------
__global__ void wprep_kernel(const float* __restrict__ wl1,
                             const float* __restrict__ wr1,
                             const float* __restrict__ wl2,
                             const float* __restrict__ wr2) {
    int i = blockIdx.x * blockDim.x + threadIdx.x;
    if (i < 128 * 128) {
        int k = i >> 7, n = i & 127;
        int o = n * 128 + k;
        splitw(wl1[i], &g_wlh[o], &g_wll[o]);
        splitw(wr1[i], &g_wrh[o], &g_wrl[o]);
    } else if (i < 128 * 128 + 80 * 128) {
        int j = i - 128 * 128;
        int n = j >> 7, k = j & 127;
        float v = (n < CLS) ? wl2[k * CLS + n] : wr2[k * CLS + (n - CLS)];
        splitw(v, &g_w2h[j], &g_w2l[j]);
    }
}

// ---------------- layer 1 GEMM via mma.sync bf16 (split, fp32 accum) ----
#define BROW_BYTES 272        // 136 bf16; conflict-free frag loads
#define BTILE_BYTES (128 * BROW_BYTES)
#define G1_SMEM (4 * BTILE_BYTES)

__global__ __launch_bounds__(512) void gemm1_mma_kernel(const float* __restrict__ x) {
    extern __shared__ char smc[];
    {
        const __nv_bfloat16* gsrc[4] = {g_wlh, g_wll, g_wrh, g_wrl};
        #pragma unroll
        for (int tsel = 0; tsel < 4; tsel++) {
            const uint4* s = reinterpret_cast<const uint4*>(gsrc[tsel]);
            char* d = smc + tsel * BTILE_BYTES;
            for (int j = threadIdx.x; j < 128 * 16; j += 512) {
                int row = j >> 4, q = j & 15;
                *reinterpret_cast<uint4*>(d + row * BROW_BYTES + q * 16) = s[j];
            }
        }
    }
    int lane = threadIdx.x & 31, wid = threadIdx.x >> 5;
    int g = lane >> 2, tg = lane & 3;
    int mw = wid & 7, nh = wid >> 3;
    int rowg  = blockIdx.x * 128 + mw * 16 + g;
    int rowg8 = rowg + 8;
    int r0 = (rowg  < NN) ? rowg  : (NN - 1);
    int r8 = (rowg8 < NN) ? rowg8 : (NN - 1);
    const float* xr0 = x + (size_t)r0 * D1;
    const float* xr8 = x + (size_t)r8 * D1;

    uint32_t ah[8][4], al[8][4];
    #pragma unroll
    for (int kc = 0; kc < 8; kc++) {
        int k0 = kc * 16 + 2 * tg;
        split2(*reinterpret_cast<const float2*>(xr0 + k0),     ah[kc][0], al[kc][0]);
        split2(*reinterpret_cast<const float2*>(xr8 + k0),     ah[kc][1], al[kc][1]);
        split2(*reinterpret_cast<const float2*>(xr0 + k0 + 8), ah[kc][2], al[kc][2]);
        split2(*reinterpret_cast<const float2*>(xr8 + k0 + 8), ah[kc][3], al[kc][3]);
    }
    __syncthreads();

    #pragma unroll
    for (int wsel = 0; wsel < 2; wsel++) {
        const char* BH = smc + (wsel * 2 + 0) * BTILE_BYTES;
        const char* BL = smc + (wsel * 2 + 1) * BTILE_BYTES;
        float acc[8][4];
        #pragma unroll
        for (int nt = 0; nt < 8; nt++)
            acc[nt][0] = acc[nt][1] = acc[nt][2] = acc[nt][3] = 0.f;
        #pragma unroll
        for (int kc = 0; kc < 8; kc++) {
            int kb = kc * 32 + tg * 4;
            #pragma unroll
            for (int nt = 0; nt < 8; nt++) {
                int nrow = nh * 64 + nt * 8 + g;
                const char* ph = BH + nrow * BROW_BYTES + kb;
                const char* pl = BL + nrow * BROW_BYTES + kb;
                uint32_t bh0 = *reinterpret_cast<const uint32_t*>(ph);
                uint32_t bh1 = *reinterpret_cast<const uint32_t*>(ph + 16);
                uint32_t bl0 = *reinterpret_cast<const uint32_t*>(pl);
                uint32_t bl1 = *reinterpret_cast<const uint32_t*>(pl + 16);
                MMA_BF16(acc[nt], ah[kc], bh0, bh1);
                MMA_BF16(acc[nt], al[kc], bh0, bh1);
                MMA_BF16(acc[nt], ah[kc], bl0, bl1);
            }
        }
        #pragma unroll
        for (int nt = 0; nt < 8; nt++) {
            int col = nh * 64 + nt * 8 + 2 * tg;
            if (wsel == 0) {   // xl1 -> fp16 (gathered operand)
                __half2 h01 = __floats2half2_rn(acc[nt][0], acc[nt][1]);
                __half2 h23 = __floats2half2_rn(acc[nt][2], acc[nt][3]);
                if (rowg < NN)
                    *reinterpret_cast<__half2*>(g_xl1h + (size_t)rowg * D1 + col) = h01;
                if (rowg8 < NN)
                    *reinterpret_cast<__half2*>(g_xl1h + (size_t)rowg8 * D1 + col) = h23;
            } else {           // xr1 -> fp32
                if (rowg < NN)
                    *reinterpret_cast<float2*>(g_xr1 + (size_t)rowg * D1 + col) =
                        make_float2(acc[nt][0], acc[nt][1]);
                if (rowg8 < NN)
                    *reinterpret_cast<float2*>(g_xr1 + (size_t)rowg8 * D1 + col) =
                        make_float2(acc[nt][2], acc[nt][3]);
            }
        }
    }
}

// ---------------- layer 2 GEMM via mma.sync (N=80 stacked) --------------
#define B2TILE (80 * BROW_BYTES)
#define G2_SMEM (2 * B2TILE)

__global__ __launch_bounds__(512) void gemm2_mma_kernel(int nbeg, int nend) {
    extern __shared__ char smc[];
    {
        const __nv_bfloat16* gsrc[2] = {g_w2h, g_w2l};
        #pragma unroll
        for (int tsel = 0; tsel < 2; tsel++) {
            const uint4* s = reinterpret_cast<const uint4*>(gsrc[tsel]);
            char* d = smc + tsel * B2TILE;
            for (int j = threadIdx.x; j < 80 * 16; j += 512) {
                int row = j >> 4, q = j & 15;
                *reinterpret_cast<uint4*>(d + row * BROW_BYTES + q * 16) = s[j];
            }
        }
    }
    int lane = threadIdx.x & 31, wid = threadIdx.x >> 5;
    int g = lane >> 2, tg = lane & 3;
    int mw = wid & 7, nh = wid >> 3;
    int rowg  = nbeg + blockIdx.x * 128 + mw * 16 + g;
    int rowg8 = rowg + 8;
    int r0 = (rowg  < NN) ? rowg  : (NN - 1);
    int r8 = (rowg8 < NN) ? rowg8 : (NN - 1);
    const float* hr0 = g_h + (size_t)r0 * D1;
    const float* hr8 = g_h + (size_t)r8 * D1;

    uint32_t ah[8][4], al[8][4];
    #pragma unroll
    for (int kc = 0; kc < 8; kc++) {
        int k0 = kc * 16 + 2 * tg;
        split2(*reinterpret_cast<const float2*>(hr0 + k0),     ah[kc][0], al[kc][0]);
        split2(*reinterpret_cast<const float2*>(hr8 + k0),     ah[kc][1], al[kc][1]);
        split2(*reinterpret_cast<const float2*>(hr0 + k0 + 8), ah[kc][2], al[kc][2]);
        split2(*reinterpret_cast<const float2*>(hr8 + k0 + 8), ah[kc][3], al[kc][3]);
    }
    __syncthreads();

    float acc[5][4];
    #pragma unroll
    for (int nt = 0; nt < 5; nt++)
        acc[nt][0] = acc[nt][1] = acc[nt][2] = acc[nt][3] = 0.f;
    #pragma unroll
    for (int kc = 0; kc < 8; kc++) {
        int kb = kc * 32 + tg * 4;
        #pragma unroll
        for (int nt = 0; nt < 5; nt++) {
            int nrow = nh * 40 + nt * 8 + g;
            const char* ph = smc + nrow * BROW_BYTES + kb;
            const char* pl = ph + B2TILE;
            uint32_t bh0 = *reinterpret_cast<const uint32_t*>(ph);
            uint32_t bh1 = *reinterpret_cast<const uint32_t*>(ph + 16);
            uint32_t bl0 = *reinterpret_cast<const uint32_t*>(pl);
            uint32_t bl1 = *reinterpret_cast<const uint32_t*>(pl + 16);
            MMA_BF16(acc[nt], ah[kc], bh0, bh1);
            MMA_BF16(acc[nt], al[kc], bh0, bh1);
            MMA_BF16(acc[nt], ah[kc], bl0, bl1);
        }
    }
    #pragma unroll
    for (int nt = 0; nt < 5; nt++) {
        int col = nt * 8 + 2 * tg;   // 0..39
        if (nh == 0) {    // xl2 -> fp16 (gathered operand)
            __half2 h01 = __floats2half2_rn(acc[nt][0], acc[nt][1]);
            __half2 h23 = __floats2half2_rn(acc[nt][2], acc[nt][3]);
            if (rowg < nend)
                *reinterpret_cast<__half2*>(g_xl2h + (size_t)rowg * CLS + col) = h01;
            if (rowg8 < nend)
                *reinterpret_cast<__half2*>(g_xl2h + (size_t)rowg8 * CLS + col) = h23;
        } else {          // xr2 -> fp32
            if (rowg < nend)
                *reinterpret_cast<float2*>(g_xr2 + (size_t)rowg * CLS + col) =
                    make_float2(acc[nt][0], acc[nt][1]);
            if (rowg8 < nend)
                *reinterpret_cast<float2*>(g_xr2 + (size_t)rowg8 * CLS + col) =
                    make_float2(acc[nt][2], acc[nt][3]);
        }
    }
}

// ---------------- fused node kernel, layer 1 (depth-4, fp16 gather) -----
__global__ void node1_kernel(const float* __restrict__ a1,
                             const float* __restrict__ b1,
                             int nbeg, int nend) {
    int n = nbeg + ((blockIdx.x * blockDim.x + threadIdx.x) >> 5);
    int lane = threadIdx.x & 31;
    if (n >= nend) return;
    int f0 = lane * 4;
    const float4 xr4 = *reinterpret_cast<const float4*>(&g_xr1[(size_t)n * D1 + f0]);
    const float4 a4  = __ldg(reinterpret_cast<const float4*>(&a1[f0]));
    int beg = g_rowptr[n];
    int cnt = g_rowptr[n + 1] - beg;
    const int* cs = g_csrc + beg;

    float den0 = 0.f, den1 = 0.f;
    float ax = 0.f, ay = 0.f, az = 0.f, aw = 0.f;

    #define G1RAW(i) (*reinterpret_cast<const uint2*>(g_xl1h + (size_t)(i) * D1 + f0))
    int idx0 = cs[0];
    int idx1 = (1 < cnt) ? cs[1] : 0;
    int idx2 = (2 < cnt) ? cs[2] : 0;
    int idx3 = (3 < cnt) ? cs[3] : 0;
    uint2 r0 = G1RAW(idx0);
    uint2 r1 = G1RAW(idx1);
    uint2 r2 = G1RAW(idx2);
    uint2 r3 = G1RAW(idx3);

    int j = 0;
    for (; j + 1 < cnt; j += 2) {
        int i4 = (j + 4 < cnt) ? cs[j + 4] : 0;
        int i5 = (j + 5 < cnt) ? cs[j + 5] : 0;
        const uint2 nr0 = G1RAW(i4);
        const uint2 nr1 = G1RAW(i5);

        float4 x0 = h4_to_f4(r0);
        float4 x1 = h4_to_f4(r1);
        float s0 = lrelu(x0.x + xr4.x) * a4.x
                 + lrelu(x0.y + xr4.y) * a4.y
                 + lrelu(x0.z + xr4.z) * a4.z
                 + lrelu(x0.w + xr4.w) * a4.w;
        float s1 = lrelu(x1.x + xr4.x) * a4.x
                 + lrelu(x1.y + xr4.y) * a4.y
                 + lrelu(x1.z + xr4.z) * a4.z
                 + lrelu(x1.w + xr4.w) * a4.w;
        s0 += __shfl_xor_sync(0xffffffffu, s0, 1);
        s1 += __shfl_xor_sync(0xffffffffu, s1, 1);
        s0 += __shfl_xor_sync(0xffffffffu, s0, 2);
        s1 += __shfl_xor_sync(0xffffffffu, s1, 2);
        s0 += __shfl_xor_sync(0xffffffffu, s0, 4);
        s1 += __shfl_xor_sync(0xffffffffu, s1, 4);
        float p0 = __expf(s0);
        float p1 = __expf(s1);
        den0 += p0; den1 += p1;
        ax = fmaf(p0, x0.x, ax); ay = fmaf(p0, x0.y, ay);
        az = fmaf(p0, x0.z, az); aw = fmaf(p0, x0.w, aw);
        ax = fmaf(p1, x1.x, ax); ay = fmaf(p1, x1.y, ay);
        az = fmaf(p1, x1.z, az); aw = fmaf(p1, x1.w, aw);
        r0 = r2; r1 = r3; r2 = nr0; r3 = nr1;
    }
    if (j < cnt) {
        float4 x0 = h4_to_f4(r0);
        float s0 = lrelu(x0.x + xr4.x) * a4.x
                 + lrelu(x0.y + xr4.y) * a4.y
                 + lrelu(x0.z + xr4.z) * a4.z
                 + lrelu(x0.w + xr4.w) * a4.w;
        s0 += __shfl_xor_sync(0xffffffffu, s0, 1);
        s0 += __shfl_xor_sync(0xffffffffu, s0, 2);
        s0 += __shfl_xor_sync(0xffffffffu, s0, 4);
        float p0 = __expf(s0);
        den0 += p0;
        ax = fmaf(p0, x0.x, ax); ay = fmaf(p0, x0.y, ay);
        az = fmaf(p0, x0.z, az); aw = fmaf(p0, x0.w, aw);
    }
    float inv = 1.f / (den0 + den1);
    const float4 b4 = __ldg(reinterpret_cast<const float4*>(&b1[f0]));
    float4 o;
    o.x = ax * inv + b4.x; o.x = (o.x > 0.f) ? o.x : (__expf(o.x) - 1.f);
    o.y = ay * inv + b4.y; o.y = (o.y > 0.f) ? o.y : (__expf(o.y) - 1.f);
    o.z = az * inv + b4.z; o.z = (o.z > 0.f) ? o.z : (__expf(o.z) - 1.f);
    o.w = aw * inv + b4.w; o.w = (o.w > 0.f) ? o.w : (__expf(o.w) - 1.f);
    *reinterpret_cast<float4*>(&g_h[(size_t)n * D1 + f0]) = o;
}

// ---------------- fused node kernel, layer 2 + log_softmax --------------
__global__ void node2_kernel(const float* __restrict__ a2,
                             const float* __restrict__ b2,
                             float* __restrict__ out) {
    int n = (blockIdx.x * blockDim.x + threadIdx.x) >> 5;
    int lane = threadIdx.x & 31;
    if (n >= NN) return;
    bool act = (lane * 2) < CLS;
    int f0 = lane * 2;
    float2 xr2v = make_float2(0.f, 0.f), a2v = make_float2(0.f, 0.f);
    if (act) {
        xr2v = *reinterpret_cast<const float2*>(&g_xr2[(size_t)n * CLS + f0]);
        a2v  = __ldg(reinterpret_cast<const float2*>(&a2[f0]));
    }
    int beg = g_rowptr[n];
    int cnt = g_rowptr[n + 1] - beg;
    const int* cs = g_csrc + beg;

    float den0 = 0.f, den1 = 0.f, ax = 0.f, ay = 0.f;

    #define G2RAW(i) (act ? *reinterpret_cast<const uint32_t*>(g_xl2h + (size_t)(i) * CLS + f0) : 0u)
    int idx0 = cs[0];
    int idx1 = (1 < cnt) ? cs[1] : 0;
    int idx2 = (2 < cnt) ? cs[2] : 0;
    int idx3 = (3 < cnt) ? cs[3] : 0;
    uint32_t r0 = G2RAW(idx0);
    uint32_t r1 = G2RAW(idx1);
    uint32_t r2 = G2RAW(idx2);
    uint32_t r3 = G2RAW(idx3);

    int j = 0;
    for (; j + 1 < cnt; j += 2) {
        int i4 = (j + 4 < cnt) ? cs[j + 4] : 0;
        int i5 = (j + 5 < cnt) ? cs[j + 5] : 0;
        const uint32_t nr0 = G2RAW(i4);
        const uint32_t nr1 = G2RAW(i5);

        float2 x0 = h2_to_f2(r0);
        float2 x1 = h2_to_f2(r1);
        float s0 = lrelu(x0.x + xr2v.x) * a2v.x + lrelu(x0.y + xr2v.y) * a2v.y;
        float s1 = lrelu(x1.x + xr2v.x) * a2v.x + lrelu(x1.y + xr2v.y) * a2v.y;
        #pragma unroll
        for (int off = 16; off > 0; off >>= 1) {
            s0 += __shfl_xor_sync(0xffffffffu, s0, off);
            s1 += __shfl_xor_sync(0xffffffffu, s1, off);
        }
        float p0 = __expf(s0);
        float p1 = __expf(s1);
        den0 += p0; den1 += p1;
        ax = fmaf(p0, x0.x, ax); ay = fmaf(p0, x0.y, ay);
        ax = fmaf(p1, x1.x, ax); ay = fmaf(p1, x1.y, ay);
        r0 = r2; r1 = r3; r2 = nr0; r3 = nr1;
    }
    if (j < cnt) {
        float2 x0 = h2_to_f2(r0);
        float s0 = lrelu(x0.x + xr2v.x) * a2v.x + lrelu(x0.y + xr2v.y) * a2v.y;
        #pragma unroll
        for (int off = 16; off > 0; off >>= 1)
            s0 += __shfl_xor_sync(0xffffffffu, s0, off);
        float p0 = __expf(s0);
        den0 += p0;
        ax = fmaf(p0, x0.x, ax); ay = fmaf(p0, x0.y, ay);
    }
    float inv = 1.f / (den0 + den1);
    float v0 = -CUDART_INF_F, v1 = -CUDART_INF_F;
    if (act) {
        v0 = ax * inv + __ldg(&b2[f0]);
        v1 = ay * inv + __ldg(&b2[f0 + 1]);
    }
    float mx = fmaxf(v0, v1);
    #pragma unroll
    for (int off = 16; off > 0; off >>= 1)
        mx = fmaxf(mx, __shfl_xor_sync(0xffffffffu, mx, off));
    float se = act ? (__expf(v0 - mx) + __expf(v1 - mx)) : 0.f;
    #pragma unroll
    for (int off = 16; off > 0; off >>= 1)
        se += __shfl_xor_sync(0xffffffffu, se, off);
    float lse = mx + logf(se);
    if (act) {
        float2 o = make_float2(v0 - lse, v1 - lse);
        *reinterpret_cast<float2*>(&out[(size_t)n * CLS + f0]) = o;
    }
}

// ---------------- stream/event objects (created at process start) -------
static cudaStream_t s_side;
static cudaEvent_t  s_ev_fork;
static cudaEvent_t  s_ev_join;
static cudaEvent_t  s_ev_h;
static cudaEvent_t  s_ev_g2a;
namespace {
struct StreamInit {
    StreamInit() {
        cudaStreamCreateWithFlags(&s_side, cudaStreamNonBlocking);
        cudaEventCreateWithFlags(&s_ev_fork, cudaEventDisableTiming);
        cudaEventCreateWithFlags(&s_ev_join, cudaEventDisableTiming);
        cudaEventCreateWithFlags(&s_ev_h, cudaEventDisableTiming);
        cudaEventCreateWithFlags(&s_ev_g2a, cudaEventDisableTiming);
        cudaFuncSetAttribute(gemm1_mma_kernel,
                             cudaFuncAttributeMaxDynamicSharedMemorySize, G1_SMEM);
        cudaFuncSetAttribute(gemm2_mma_kernel,
                             cudaFuncAttributeMaxDynamicSharedMemorySize, G2_SMEM);
    }
};
static StreamInit s_stream_init;
}

// ---------------- launch ----------------
extern "C" void kernel_launch(void* const* d_in, const int* in_sizes, int n_in,
                              void* d_out, int out_size) {
    const float* x    = (const float*)d_in[0];
    const int*   eiw  = (const int*)d_in[1];
    const float* w1_l = (const float*)d_in[2];
    const float* w1_r = (const float*)d_in[3];
    const float* a1   = (const float*)d_in[4];
    const float* b1   = (const float*)d_in[5];
    const float* w2_l = (const float*)d_in[6];
    const float* w2_r = (const float*)d_in[7];
    const float* a2   = (const float*)d_in[8];
    const float* b2   = (const float*)d_in[9];
    float*       out  = (float*)d_out;

    // fork: CSR build on side stream, weight prep + gemm1 on main stream
    cudaEventRecord(s_ev_fork, 0);
    cudaStreamWaitEvent(s_side, s_ev_fork, 0);

    conv_hist_kernel<<<(ET + 255) / 256, 256, 0, s_side>>>(eiw);
    scan1_kernel<<<NBLK, SCANB, 0, s_side>>>();
    scan3_kernel<<<(NN + 255) / 256, 256, 0, s_side>>>();
    scatter_kernel<<<(ET + 255) / 256, 256, 0, s_side>>>();
    cudaEventRecord(s_ev_join, s_side);

    wprep_kernel<<<(128 * 128 + 80 * 128 + 255) / 256, 256>>>(w1_l, w1_r, w2_l, w2_r);
    gemm1_mma_kernel<<<(NN + 127) / 128, 512, G1_SMEM>>>(x);

    // join CSR
    cudaStreamWaitEvent(0, s_ev_join, 0);

    node1_kernel<<<(NHALF * 32) / 256, 256>>>(a1, b1, 0, NHALF);
    cudaEventRecord(s_ev_h, 0);
    cudaStreamWaitEvent(s_side, s_ev_h, 0);
    gemm2_mma_kernel<<<NHALF / 128, 512, G2_SMEM, s_side>>>(0, NHALF);
    cudaEventRecord(s_ev_g2a, s_side);

    node1_kernel<<<((NN - NHALF) * 32 + 255) / 256, 256>>>(a1, b1, NHALF, NN);
    gemm2_mma_kernel<<<(NN - NHALF + 127) / 128, 512, G2_SMEM>>>(NHALF, NN);

    cudaStreamWaitEvent(0, s_ev_g2a, 0);
    node2_kernel<<<(NN * 32 + 255) / 256, 256>>>(a2, b2, out);
}